// round 6
// baseline (speedup 1.0000x reference)
#include <cuda_runtime.h>
#include <cuda_bf16.h>
#include <math.h>

// Problem constants
#define BB 4
#define TT 1024
#define CC 2048
#define HH 16
#define DD 128
#define MM (BB*TT)          // 4096
#define KK CC               // 2048
#define N_QKV (3*CC)        // 6144
#define N_PROJ CC           // 2048

// Scratch (device globals; no runtime allocation)
__device__ float g_q[BB*HH*TT*DD];
__device__ float g_k[BB*HH*TT*DD];
__device__ float g_v[BB*HH*TT*DD];
__device__ float g_y[MM*CC];

// Canonicalized quantized params (immune to harness dtype promotion)
__device__ signed char g_wa8[(size_t)N_QKV*KK];   // 12.6 MB
__device__ signed char g_wp8[(size_t)N_PROJ*KK];  // 4.2 MB
__device__ float g_bias_a[N_QKV];
__device__ float g_bias_p[N_PROJ];
__device__ int g_flag[4];   // 0:wa 1:wp 2:ba 3:bp ; value 0=i8,1=i32,2=f32

// ---------------------------------------------------------------------------
// dtype detection: classify a buffer's storage as int8 / int32 / float32
// ---------------------------------------------------------------------------
__device__ int detect_words(const unsigned int* w, int nwords)
{
    bool i32 = true, f32 = true;
    for (int i = 0; i < nwords; ++i) {
        unsigned int v = w[i];
        if (!(v < 0x80u || v >= 0xFFFFFF80u)) i32 = false;
        float f = __uint_as_float(v);
        if (!(fabsf(f) <= 128.0f && f == truncf(f))) f32 = false; // NaN fails
        if (!i32 && !f32) break;
    }
    return i32 ? 1 : (f32 ? 2 : 0);
}

__global__ void detect_kernel(const void* wa, const void* wp,
                              const void* ba, const void* bp)
{
    const int t = threadIdx.x;
    if (t == 0) g_flag[0] = detect_words((const unsigned int*)wa, 256);
    if (t == 1) g_flag[1] = detect_words((const unsigned int*)wp, 256);
    if (t == 2) g_flag[2] = detect_words((const unsigned int*)ba, 256);
    if (t == 3) g_flag[3] = detect_words((const unsigned int*)bp, 256);
}

// ---------------------------------------------------------------------------
// canonicalize weights -> int8, biases -> float (pre-scaled by s_b)
// ---------------------------------------------------------------------------
__global__ void convert_w_kernel(const void* src, signed char* dst,
                                 int flag_idx, size_t n)
{
    const int f = g_flag[flag_idx];
    const size_t stride = (size_t)gridDim.x * blockDim.x;
    for (size_t i = (size_t)blockIdx.x*blockDim.x + threadIdx.x; i < n; i += stride) {
        int v;
        if (f == 1)      v = ((const int*)src)[i];
        else if (f == 2) v = __float2int_rn(((const float*)src)[i]);
        else             v = ((const signed char*)src)[i];
        dst[i] = (signed char)v;
    }
}

__global__ void convert_bias_kernel(const void* src, const float* s,
                                    float* dst, int flag_idx, int n)
{
    const int f = g_flag[flag_idx];
    const float sb = s[0];
    for (int i = blockIdx.x*blockDim.x + threadIdx.x; i < n;
         i += gridDim.x*blockDim.x) {
        int v;
        if (f == 1)      v = ((const int*)src)[i];
        else if (f == 2) v = __float2int_rn(((const float*)src)[i]);
        else             v = ((const signed char*)src)[i];
        dst[i] = sb * (float)v;
    }
}

// ---------------------------------------------------------------------------
// SGEMM: C[m,o] = sw * sum_k A[m,k]*Bq[o,k] + bias[o]   (zero-points = 0)
// A row-major [M,K] fp32, Bq row-major [N,K] int8. BM=BN=128, BK=16, 8x8 micro.
// MODE 0: A = x, scatter into g_q/g_k/g_v.  MODE 1: A = g_y, store to out.
// ---------------------------------------------------------------------------
template<int MODE>
__global__ void __launch_bounds__(256) sgemm_kernel(
    const float* __restrict__ A,
    const signed char* __restrict__ Bq,
    const float* __restrict__ sW,
    const float* __restrict__ biasf,
    float* __restrict__ out, int Nn)
{
    __shared__ float As[16][132];
    __shared__ float Bs[16][132];

    const int tid = threadIdx.x;
    const int bx = blockIdx.x;   // N tile
    const int by = blockIdx.y;   // M tile

    const float* Ap = (MODE == 0) ? A : g_y;

    const int arow = tid >> 2;          // 0..63
    const int k4   = (tid & 3);         // which float4 within BK=16
    const float* aptr = Ap + (size_t)(by*128 + arow)*KK + k4*4;
    const signed char* bptr = Bq + (size_t)(bx*128 + arow)*KK + k4*4;

    const int tx = tid & 15;
    const int ty = tid >> 4;

    float acc[8][8];
#pragma unroll
    for (int i = 0; i < 8; i++)
#pragma unroll
        for (int j = 0; j < 8; j++) acc[i][j] = 0.f;

    for (int kt = 0; kt < KK/16; ++kt) {
        float4 a0 = *(const float4*)(aptr);
        float4 a1 = *(const float4*)(aptr + 64*KK);
        char4  b0 = *(const char4*)(bptr);
        char4  b1 = *(const char4*)(bptr + 64*KK);

        const int k0 = k4*4;
        As[k0+0][arow]    = a0.x; As[k0+1][arow]    = a0.y;
        As[k0+2][arow]    = a0.z; As[k0+3][arow]    = a0.w;
        As[k0+0][arow+64] = a1.x; As[k0+1][arow+64] = a1.y;
        As[k0+2][arow+64] = a1.z; As[k0+3][arow+64] = a1.w;
        Bs[k0+0][arow]    = (float)b0.x; Bs[k0+1][arow]    = (float)b0.y;
        Bs[k0+2][arow]    = (float)b0.z; Bs[k0+3][arow]    = (float)b0.w;
        Bs[k0+0][arow+64] = (float)b1.x; Bs[k0+1][arow+64] = (float)b1.y;
        Bs[k0+2][arow+64] = (float)b1.z; Bs[k0+3][arow+64] = (float)b1.w;
        __syncthreads();

#pragma unroll
        for (int kk = 0; kk < 16; ++kk) {
            float4 af0 = *(const float4*)&As[kk][ty*8];
            float4 af1 = *(const float4*)&As[kk][ty*8+4];
            float4 bf0 = *(const float4*)&Bs[kk][tx*8];
            float4 bf1 = *(const float4*)&Bs[kk][tx*8+4];
            float a[8] = {af0.x, af0.y, af0.z, af0.w, af1.x, af1.y, af1.z, af1.w};
            float b[8] = {bf0.x, bf0.y, bf0.z, bf0.w, bf1.x, bf1.y, bf1.z, bf1.w};
#pragma unroll
            for (int i = 0; i < 8; i++)
#pragma unroll
                for (int j = 0; j < 8; j++)
                    acc[i][j] = fmaf(a[i], b[j], acc[i][j]);
        }
        __syncthreads();
        aptr += 16;
        bptr += 16;
    }

    const float sw = sW[0];

#pragma unroll
    for (int i = 0; i < 8; i++) {
        const int m = by*128 + ty*8 + i;
#pragma unroll
        for (int j = 0; j < 8; j++) {
            const int o = bx*128 + tx*8 + j;
            const float v = sw * acc[i][j] + biasf[o];
            if (MODE == 1) {
                out[(size_t)m*Nn + o] = v;
            } else {
                const int which = o >> 11;       // 0:q 1:k 2:v
                const int c = o & 2047;
                const int h = c >> 7;
                const int d = c & 127;
                const int b = m >> 10;
                const int t = m & 1023;
                float* dst = (which == 0) ? g_q : (which == 1) ? g_k : g_v;
                dst[(size_t)(((b*HH + h)*TT + t))*DD + d] = v;
            }
        }
    }
}

// ---------------------------------------------------------------------------
// Flash attention, STATIC smem (<48KB). Block = (b,h) x 64-query tile, 256 thr.
// Thread (si=tid>>2, sjg=tid&3): Q row si, d-chunk [sjg*32, sjg*32+32).
// K/V tiles 32x128 in smem; score partial dot shfl-reduced over 4-lane group;
// softmax state in registers (replicated across the quad).
// ---------------------------------------------------------------------------
__global__ void __launch_bounds__(256) attn_kernel()
{
    __shared__ float Ks[32][132];
    __shared__ float Vs[32][132];

    const int bh = blockIdx.x;   // b*H + h   (64)
    const int qt = blockIdx.y;   // query tile (16), 64 rows each
    const int tid = threadIdx.x;
    const int si  = tid >> 2;    // q row in tile [0,64)
    const int sjg = tid & 3;     // d-chunk [0,4)

    const float scale = 0.088388347648318447f; // 1/sqrt(128)

    float4 qreg[8];
    {
        const float4* qsrc = (const float4*)(g_q + (size_t)bh*TT*DD
                                             + (size_t)(qt*64 + si)*DD + sjg*32);
#pragma unroll
        for (int i = 0; i < 8; ++i) qreg[i] = qsrc[i];
    }

    float oacc[32];
#pragma unroll
    for (int c = 0; c < 32; ++c) oacc[c] = 0.f;
    float m_run = -INFINITY;
    float l_run = 0.f;

    const int tglob = qt*64 + si;
    const int nkt = 2*qt + 2;    // number of 32-row K tiles

    for (int kt = 0; kt < nkt; ++kt) {
        __syncthreads();
        {
            const float4* ksrc = (const float4*)(g_k + (size_t)bh*TT*DD + (size_t)kt*32*DD);
            const float4* vsrc = (const float4*)(g_v + (size_t)bh*TT*DD + (size_t)kt*32*DD);
#pragma unroll
            for (int it = 0; it < 4; ++it) {
                int idx = tid + it*256;      // 1024 float4 = 32x128 floats
                int r = idx >> 5, c4 = idx & 31;
                *(float4*)&Ks[r][c4*4] = ksrc[idx];
                *(float4*)&Vs[r][c4*4] = vsrc[idx];
            }
        }
        __syncthreads();

        float sv[32];
#pragma unroll
        for (int j = 0; j < 32; ++j) {
            const float4* krow = (const float4*)&Ks[j][sjg*32];
            float s = 0.f;
#pragma unroll
            for (int d4 = 0; d4 < 8; ++d4) {
                float4 k4 = krow[d4];
                float4 q4 = qreg[d4];
                s = fmaf(q4.x, k4.x, s);
                s = fmaf(q4.y, k4.y, s);
                s = fmaf(q4.z, k4.z, s);
                s = fmaf(q4.w, k4.w, s);
            }
            s += __shfl_xor_sync(0xffffffffu, s, 1);
            s += __shfl_xor_sync(0xffffffffu, s, 2);
            sv[j] = s;
        }

        float mloc = -INFINITY;
#pragma unroll
        for (int j = 0; j < 32; ++j) {
            const int jg = kt*32 + j;
            sv[j] = (jg <= tglob) ? sv[j]*scale : -INFINITY;
            mloc = fmaxf(mloc, sv[j]);
        }
        const float mnew  = fmaxf(m_run, mloc);
        const float alpha = __expf(m_run - mnew);

        float lsum = 0.f;
#pragma unroll
        for (int j = 0; j < 32; ++j) {
            sv[j] = __expf(sv[j] - mnew);
            lsum += sv[j];
        }
        l_run = l_run*alpha + lsum;
        m_run = mnew;

#pragma unroll
        for (int c = 0; c < 32; ++c) oacc[c] *= alpha;

#pragma unroll
        for (int j = 0; j < 32; ++j) {
            const float pj = sv[j];
            const float4* vrow = (const float4*)&Vs[j][sjg*32];
#pragma unroll
            for (int d4 = 0; d4 < 8; ++d4) {
                float4 v4 = vrow[d4];
                oacc[d4*4+0] = fmaf(pj, v4.x, oacc[d4*4+0]);
                oacc[d4*4+1] = fmaf(pj, v4.y, oacc[d4*4+1]);
                oacc[d4*4+2] = fmaf(pj, v4.z, oacc[d4*4+2]);
                oacc[d4*4+3] = fmaf(pj, v4.w, oacc[d4*4+3]);
            }
        }
    }

    const float linv = 1.0f / l_run;
    const int b = bh >> 4;
    const int h = bh & 15;
    const int t = qt*64 + si;
    float* dst = g_y + (size_t)(b*TT + t)*CC + h*DD + sjg*32;
#pragma unroll
    for (int d4 = 0; d4 < 8; ++d4) {
        float4 v;
        v.x = oacc[d4*4+0]*linv;
        v.y = oacc[d4*4+1]*linv;
        v.z = oacc[d4*4+2]*linv;
        v.w = oacc[d4*4+3]*linv;
        *(float4*)(dst + d4*4) = v;
    }
}

// ---------------------------------------------------------------------------
extern "C" void kernel_launch(void* const* d_in, const int* in_sizes, int n_in,
                              void* d_out, int out_size)
{
    // Input resolution by element count (immune to scalar serialization).
    // Zero points are mathematically 0 for symmetric range -> ignored.
    int i_x = -1, i_wa = -1, i_ba = -1, i_wp = -1, i_bp = -1;
    for (int i = 0; i < n_in; ++i) {
        switch (in_sizes[i]) {
            case 8388608:  i_x  = i; break;   // x [4,1024,2048] f32
            case 12582912: i_wa = i; break;   // w_attn_q [6144,2048]
            case 6144:     i_ba = i; break;   // b_attn_q
            case 4194304:  i_wp = i; break;   // w_proj_q [2048,2048]
            case 2048:     i_bp = i; break;   // b_proj_q
            default: break;
        }
    }
    auto find_scale = [&](int start) -> int {
        for (int j = start + 1; j < n_in; ++j)
            if (in_sizes[j] <= 1) return j;
        return -1;
    };
    const int i_swa = find_scale(i_wa);
    const int i_sba = find_scale(i_ba);
    const int i_swp = find_scale(i_wp);
    const int i_sbp = find_scale(i_bp);

    const float* x        = (const float*)d_in[i_x];
    const void*  w_attn_q = d_in[i_wa];
    const float* s_w_attn = (const float*)d_in[i_swa];
    const void*  b_attn_q = d_in[i_ba];
    const float* s_b_attn = (const float*)d_in[i_sba];
    const void*  w_proj_q = d_in[i_wp];
    const float* s_w_proj = (const float*)d_in[i_swp];
    const void*  b_proj_q = d_in[i_bp];
    const float* s_b_proj = (const float*)d_in[i_sbp];
    float* out = (float*)d_out;

    // Stage 0: detect quantized-buffer storage dtype, canonicalize.
    detect_kernel<<<1, 4>>>(w_attn_q, w_proj_q, b_attn_q, b_proj_q);
    {
        signed char* wa8; cudaGetSymbolAddress((void**)&wa8, g_wa8);
        signed char* wp8; cudaGetSymbolAddress((void**)&wp8, g_wp8);
        float* ba;        cudaGetSymbolAddress((void**)&ba,  g_bias_a);
        float* bp;        cudaGetSymbolAddress((void**)&bp,  g_bias_p);
        convert_w_kernel<<<512, 256>>>(w_attn_q, wa8, 0, (size_t)N_QKV*KK);
        convert_w_kernel<<<512, 256>>>(w_proj_q, wp8, 1, (size_t)N_PROJ*KK);
        convert_bias_kernel<<<12, 256>>>(b_attn_q, s_b_attn, ba, 2, N_QKV);
        convert_bias_kernel<<<8, 256>>>(b_proj_q, s_b_proj, bp, 3, N_PROJ);

        // Stage 1: QKV projection with fused dequant, scatter to [B,H,T,D]
        {
            dim3 grid(N_QKV/128, MM/128);
            sgemm_kernel<0><<<grid, 256>>>(x, wa8, s_w_attn, ba, nullptr, N_QKV);
        }

        // Stage 2: causal flash attention -> g_y [B,T,C]
        {
            dim3 grid(BB*HH, TT/64);
            attn_kernel<<<grid, 256>>>();
        }

        // Stage 3: output projection -> d_out
        {
            dim3 grid(N_PROJ/128, MM/128);
            sgemm_kernel<1><<<grid, 256>>>(nullptr, wp8, s_w_proj, bp, out, N_PROJ);
        }
    }
}

// round 7
// speedup vs baseline: 1.5353x; 1.5353x over previous
#include <cuda_runtime.h>
#include <cuda_bf16.h>
#include <math.h>
#include <stdint.h>

// Problem constants
#define BB 4
#define TT 1024
#define CC 2048
#define HH 16
#define DD 128
#define MM (BB*TT)          // 4096
#define KK CC               // 2048
#define N_QKV (3*CC)        // 6144
#define N_PROJ CC           // 2048

// Scratch (device globals; no runtime allocation)
__device__ float g_q[BB*HH*TT*DD];
__device__ float g_k[BB*HH*TT*DD];
__device__ float g_v[BB*HH*TT*DD];
__device__ float g_y[MM*CC];

// bf16 operands
__device__ __nv_bfloat16 g_wa_bf[(size_t)N_QKV*KK];   // 25 MB
__device__ __nv_bfloat16 g_wp_bf[(size_t)N_PROJ*KK];  // 8.4 MB
__device__ __nv_bfloat16 g_xhi[(size_t)MM*KK];
__device__ __nv_bfloat16 g_xlo[(size_t)MM*KK];
__device__ __nv_bfloat16 g_yhi[(size_t)MM*KK];
__device__ __nv_bfloat16 g_ylo[(size_t)MM*KK];
__device__ float g_bias_a[N_QKV];
__device__ float g_bias_p[N_PROJ];
__device__ int g_flag[4];   // 0:wa 1:wp 2:ba 3:bp ; 0=i8,1=i32,2=f32

// ---------------------------------------------------------------------------
// dtype detection (harness may promote int8 arrays to int32/f32 storage)
// ---------------------------------------------------------------------------
__device__ int detect_words(const unsigned int* w, int nwords)
{
    bool i32 = true, f32 = true;
    for (int i = 0; i < nwords; ++i) {
        unsigned int v = w[i];
        if (!(v < 0x80u || v >= 0xFFFFFF80u)) i32 = false;
        float f = __uint_as_float(v);
        if (!(fabsf(f) <= 128.0f && f == truncf(f))) f32 = false;
        if (!i32 && !f32) break;
    }
    return i32 ? 1 : (f32 ? 2 : 0);
}

__global__ void detect_kernel(const void* wa, const void* wp,
                              const void* ba, const void* bp)
{
    const int t = threadIdx.x;
    if (t == 0) g_flag[0] = detect_words((const unsigned int*)wa, 256);
    if (t == 1) g_flag[1] = detect_words((const unsigned int*)wp, 256);
    if (t == 2) g_flag[2] = detect_words((const unsigned int*)ba, 256);
    if (t == 3) g_flag[3] = detect_words((const unsigned int*)bp, 256);
}

__device__ __forceinline__ int load_qval(const void* src, int f, size_t i)
{
    if (f == 1) return ((const int*)src)[i];
    if (f == 2) return __float2int_rn(((const float*)src)[i]);
    return (int)((const signed char*)src)[i];
}

// weights -> bf16 (exact: small integers)
__global__ void convert_w_bf16(const void* src, __nv_bfloat16* dst,
                               int flag_idx, size_t n)
{
    const int f = g_flag[flag_idx];
    const size_t stride = (size_t)gridDim.x * blockDim.x;
    for (size_t i = (size_t)blockIdx.x*blockDim.x + threadIdx.x; i < n; i += stride)
        dst[i] = __float2bfloat16_rn((float)load_qval(src, f, i));
}

// biases -> float, pre-scaled
__global__ void convert_bias_kernel(const void* src, const float* s,
                                    float* dst, int flag_idx, int n)
{
    const int f = g_flag[flag_idx];
    const float sb = s[0];
    for (int i = blockIdx.x*blockDim.x + threadIdx.x; i < n;
         i += gridDim.x*blockDim.x)
        dst[i] = sb * (float)load_qval(src, f, i);
}

// fp32 -> (hi, lo) bf16 split
__global__ void convert_hilo(const float* __restrict__ src,
                             __nv_bfloat16* __restrict__ hi,
                             __nv_bfloat16* __restrict__ lo, size_t n)
{
    const size_t stride = (size_t)gridDim.x * blockDim.x;
    for (size_t i = (size_t)blockIdx.x*blockDim.x + threadIdx.x; i < n; i += stride) {
        float v = src[i];
        __nv_bfloat16 h = __float2bfloat16_rn(v);
        hi[i] = h;
        lo[i] = __float2bfloat16_rn(v - __bfloat162float(h));
    }
}

// ---------------------------------------------------------------------------
// Tensor-core GEMM: C[m,n] = sw * sum_k (Ahi+Alo)[m,k]*W[n,k] + bias[n]
// bf16 mma.sync m16n8k16, BM=BN=128, BK=32, 8 warps (2x4), warp tile 64x32.
// MODE 0: scatter into g_q/g_k/g_v.  MODE 1: store to out.
// ---------------------------------------------------------------------------
__device__ __forceinline__ void ldsm_x4(uint32_t& r0, uint32_t& r1,
                                        uint32_t& r2, uint32_t& r3, uint32_t a)
{
    asm volatile("ldmatrix.sync.aligned.m8n8.x4.shared.b16 {%0,%1,%2,%3}, [%4];"
                 : "=r"(r0), "=r"(r1), "=r"(r2), "=r"(r3) : "r"(a));
}
__device__ __forceinline__ void ldsm_x2(uint32_t& r0, uint32_t& r1, uint32_t a)
{
    asm volatile("ldmatrix.sync.aligned.m8n8.x2.shared.b16 {%0,%1}, [%2];"
                 : "=r"(r0), "=r"(r1) : "r"(a));
}
__device__ __forceinline__ void mma_bf16(float* c, const uint32_t* a,
                                         const uint32_t* b)
{
    asm volatile(
        "mma.sync.aligned.m16n8k16.row.col.f32.bf16.bf16.f32 "
        "{%0,%1,%2,%3},{%4,%5,%6,%7},{%8,%9},{%0,%1,%2,%3};"
        : "+f"(c[0]), "+f"(c[1]), "+f"(c[2]), "+f"(c[3])
        : "r"(a[0]), "r"(a[1]), "r"(a[2]), "r"(a[3]), "r"(b[0]), "r"(b[1]));
}

#define APAD 40   // bf16 elements per smem row (32 data + 8 pad); 80B stride

template<int MODE>
__global__ void __launch_bounds__(256) bgemm_kernel(
    const float* __restrict__ sW,
    const float* __restrict__ biasf,
    float* __restrict__ out)
{
    const __nv_bfloat16* Ahi = (MODE == 0) ? g_xhi : g_yhi;
    const __nv_bfloat16* Alo = (MODE == 0) ? g_xlo : g_ylo;
    const __nv_bfloat16* Bw  = (MODE == 0) ? g_wa_bf : g_wp_bf;
    const int Nn = (MODE == 0) ? N_QKV : N_PROJ;

    __shared__ __nv_bfloat16 Ash[128][APAD];
    __shared__ __nv_bfloat16 Asl[128][APAD];
    __shared__ __nv_bfloat16 Bsh[128][APAD];

    const int tid  = threadIdx.x;
    const int bx   = blockIdx.x;   // N tile
    const int by   = blockIdx.y;   // M tile
    const int w    = tid >> 5;
    const int lane = tid & 31;
    const int wm   = w >> 2;       // 0..1
    const int wn   = w & 3;        // 0..3

    float acc[4][4][4];
#pragma unroll
    for (int i = 0; i < 4; ++i)
#pragma unroll
        for (int j = 0; j < 4; ++j)
#pragma unroll
            for (int c = 0; c < 4; ++c) acc[i][j][c] = 0.f;

    // ldmatrix base addresses (shared-space u32)
    const uint32_t a_hi_base = (uint32_t)__cvta_generic_to_shared(&Ash[0][0]);
    const uint32_t a_lo_base = (uint32_t)__cvta_generic_to_shared(&Asl[0][0]);
    const uint32_t b_base    = (uint32_t)__cvta_generic_to_shared(&Bsh[0][0]);
    // A quad layout: l/8 selects (m0k0, m8k0, m0k8, m8k8)
    const int a_row = wm*64 + ((lane >> 3) & 1)*8 + (lane & 7);
    const int a_col = (lane >> 4)*8;
    const uint32_t a_off = (uint32_t)(a_row*APAD + a_col)*2;
    // B x2 layout: lanes 0-7 -> n rows @k0, 8-15 -> @k8
    const int l2 = lane & 15;
    const int b_row = wn*32 + (l2 & 7);
    const int b_col = (l2 >> 3)*8;
    const uint32_t b_off = (uint32_t)(b_row*APAD + b_col)*2;

    for (int kt = 0; kt < KK/32; ++kt) {
        // load tiles: 128x32 bf16 each = 512 x 16B; 256 threads x 2 segs
#pragma unroll
        for (int p = 0; p < 2; ++p) {
            const int idx = tid + p*256;
            const int row = idx >> 2;
            const int seg = idx & 3;
            const size_t goff = (size_t)(by*128 + row)*KK + kt*32 + seg*8;
            *(uint4*)&Ash[row][seg*8] = *(const uint4*)(Ahi + goff);
            *(uint4*)&Asl[row][seg*8] = *(const uint4*)(Alo + goff);
            const size_t boff = (size_t)(bx*128 + row)*KK + kt*32 + seg*8;
            *(uint4*)&Bsh[row][seg*8] = *(const uint4*)(Bw + boff);
        }
        __syncthreads();

#pragma unroll
        for (int kf = 0; kf < 2; ++kf) {
            const uint32_t kfb = (uint32_t)(kf*16*2);  // 16 bf16 cols = 32 B
            uint32_t bfr[4][2];
#pragma unroll
            for (int j = 0; j < 4; ++j)
                ldsm_x2(bfr[j][0], bfr[j][1],
                        b_base + b_off + (uint32_t)(j*8*APAD*2) + kfb);
#pragma unroll
            for (int i = 0; i < 4; ++i) {
                uint32_t a[4];
                const uint32_t ao = a_off + (uint32_t)(i*16*APAD*2) + kfb;
                ldsm_x4(a[0], a[1], a[2], a[3], a_hi_base + ao);
#pragma unroll
                for (int j = 0; j < 4; ++j) mma_bf16(acc[i][j], a, bfr[j]);
                ldsm_x4(a[0], a[1], a[2], a[3], a_lo_base + ao);
#pragma unroll
                for (int j = 0; j < 4; ++j) mma_bf16(acc[i][j], a, bfr[j]);
            }
        }
        __syncthreads();
    }

    // epilogue
    const float sw = sW[0];
    const int mrow = (lane >> 2);
    const int ncol = 2*(lane & 3);
#pragma unroll
    for (int i = 0; i < 4; ++i) {
#pragma unroll
        for (int j = 0; j < 4; ++j) {
#pragma unroll
            for (int c = 0; c < 4; ++c) {
                const int m = by*128 + wm*64 + i*16 + mrow + ((c >> 1) ? 8 : 0);
                const int n = bx*128 + wn*32 + j*8 + ncol + (c & 1);
                const float v = sw * acc[i][j][c] + biasf[n];
                if (MODE == 1) {
                    out[(size_t)m*Nn + n] = v;
                } else {
                    const int which = n >> 11;       // 0:q 1:k 2:v
                    const int cc = n & 2047;
                    const int h = cc >> 7;
                    const int d = cc & 127;
                    const int b = m >> 10;
                    const int t = m & 1023;
                    float* dst = (which == 0) ? g_q : (which == 1) ? g_k : g_v;
                    dst[(size_t)(((b*HH + h)*TT + t))*DD + d] = v;
                }
            }
        }
    }
}

// ---------------------------------------------------------------------------
// Flash attention, fp32, STATIC smem. Block = (b,h) x 64-query tile, 256 thr.
// ---------------------------------------------------------------------------
__global__ void __launch_bounds__(256) attn_kernel()
{
    __shared__ float Ks[32][132];
    __shared__ float Vs[32][132];

    const int bh = blockIdx.x;
    const int qt = blockIdx.y;
    const int tid = threadIdx.x;
    const int si  = tid >> 2;
    const int sjg = tid & 3;

    const float scale = 0.088388347648318447f; // 1/sqrt(128)

    float4 qreg[8];
    {
        const float4* qsrc = (const float4*)(g_q + (size_t)bh*TT*DD
                                             + (size_t)(qt*64 + si)*DD + sjg*32);
#pragma unroll
        for (int i = 0; i < 8; ++i) qreg[i] = qsrc[i];
    }

    float oacc[32];
#pragma unroll
    for (int c = 0; c < 32; ++c) oacc[c] = 0.f;
    float m_run = -INFINITY;
    float l_run = 0.f;

    const int tglob = qt*64 + si;
    const int nkt = 2*qt + 2;

    for (int kt = 0; kt < nkt; ++kt) {
        __syncthreads();
        {
            const float4* ksrc = (const float4*)(g_k + (size_t)bh*TT*DD + (size_t)kt*32*DD);
            const float4* vsrc = (const float4*)(g_v + (size_t)bh*TT*DD + (size_t)kt*32*DD);
#pragma unroll
            for (int it = 0; it < 4; ++it) {
                int idx = tid + it*256;
                int r = idx >> 5, c4 = idx & 31;
                *(float4*)&Ks[r][c4*4] = ksrc[idx];
                *(float4*)&Vs[r][c4*4] = vsrc[idx];
            }
        }
        __syncthreads();

        float sv[32];
#pragma unroll
        for (int j = 0; j < 32; ++j) {
            const float4* krow = (const float4*)&Ks[j][sjg*32];
            float s = 0.f;
#pragma unroll
            for (int d4 = 0; d4 < 8; ++d4) {
                float4 k4 = krow[d4];
                float4 q4 = qreg[d4];
                s = fmaf(q4.x, k4.x, s);
                s = fmaf(q4.y, k4.y, s);
                s = fmaf(q4.z, k4.z, s);
                s = fmaf(q4.w, k4.w, s);
            }
            s += __shfl_xor_sync(0xffffffffu, s, 1);
            s += __shfl_xor_sync(0xffffffffu, s, 2);
            sv[j] = s;
        }

        float mloc = -INFINITY;
#pragma unroll
        for (int j = 0; j < 32; ++j) {
            const int jg = kt*32 + j;
            sv[j] = (jg <= tglob) ? sv[j]*scale : -INFINITY;
            mloc = fmaxf(mloc, sv[j]);
        }
        const float mnew  = fmaxf(m_run, mloc);
        const float alpha = __expf(m_run - mnew);

        float lsum = 0.f;
#pragma unroll
        for (int j = 0; j < 32; ++j) {
            sv[j] = __expf(sv[j] - mnew);
            lsum += sv[j];
        }
        l_run = l_run*alpha + lsum;
        m_run = mnew;

#pragma unroll
        for (int c = 0; c < 32; ++c) oacc[c] *= alpha;

#pragma unroll
        for (int j = 0; j < 32; ++j) {
            const float pj = sv[j];
            const float4* vrow = (const float4*)&Vs[j][sjg*32];
#pragma unroll
            for (int d4 = 0; d4 < 8; ++d4) {
                float4 v4 = vrow[d4];
                oacc[d4*4+0] = fmaf(pj, v4.x, oacc[d4*4+0]);
                oacc[d4*4+1] = fmaf(pj, v4.y, oacc[d4*4+1]);
                oacc[d4*4+2] = fmaf(pj, v4.z, oacc[d4*4+2]);
                oacc[d4*4+3] = fmaf(pj, v4.w, oacc[d4*4+3]);
            }
        }
    }

    const float linv = 1.0f / l_run;
    const int b = bh >> 4;
    const int h = bh & 15;
    const int t = qt*64 + si;
    float* dst = g_y + (size_t)(b*TT + t)*CC + h*DD + sjg*32;
#pragma unroll
    for (int d4 = 0; d4 < 8; ++d4) {
        float4 v;
        v.x = oacc[d4*4+0]*linv;
        v.y = oacc[d4*4+1]*linv;
        v.z = oacc[d4*4+2]*linv;
        v.w = oacc[d4*4+3]*linv;
        *(float4*)(dst + d4*4) = v;
    }
}

// ---------------------------------------------------------------------------
extern "C" void kernel_launch(void* const* d_in, const int* in_sizes, int n_in,
                              void* d_out, int out_size)
{
    int i_x = -1, i_wa = -1, i_ba = -1, i_wp = -1, i_bp = -1;
    for (int i = 0; i < n_in; ++i) {
        switch (in_sizes[i]) {
            case 8388608:  i_x  = i; break;
            case 12582912: i_wa = i; break;
            case 6144:     i_ba = i; break;
            case 4194304:  i_wp = i; break;
            case 2048:     i_bp = i; break;
            default: break;
        }
    }
    auto find_scale = [&](int start) -> int {
        for (int j = start + 1; j < n_in; ++j)
            if (in_sizes[j] <= 1) return j;
        return -1;
    };
    const int i_swa = find_scale(i_wa);
    const int i_sba = find_scale(i_ba);
    const int i_swp = find_scale(i_wp);
    const int i_sbp = find_scale(i_bp);

    const float* x        = (const float*)d_in[i_x];
    const void*  w_attn_q = d_in[i_wa];
    const float* s_w_attn = (const float*)d_in[i_swa];
    const void*  b_attn_q = d_in[i_ba];
    const float* s_b_attn = (const float*)d_in[i_sba];
    const void*  w_proj_q = d_in[i_wp];
    const float* s_w_proj = (const float*)d_in[i_swp];
    const void*  b_proj_q = d_in[i_bp];
    const float* s_b_proj = (const float*)d_in[i_sbp];
    float* out = (float*)d_out;

    __nv_bfloat16 *wa_bf, *wp_bf, *xhi, *xlo, *yhi, *ylo;
    float *ba, *bp, *y;
    cudaGetSymbolAddress((void**)&wa_bf, g_wa_bf);
    cudaGetSymbolAddress((void**)&wp_bf, g_wp_bf);
    cudaGetSymbolAddress((void**)&xhi, g_xhi);
    cudaGetSymbolAddress((void**)&xlo, g_xlo);
    cudaGetSymbolAddress((void**)&yhi, g_yhi);
    cudaGetSymbolAddress((void**)&ylo, g_ylo);
    cudaGetSymbolAddress((void**)&ba,  g_bias_a);
    cudaGetSymbolAddress((void**)&bp,  g_bias_p);
    cudaGetSymbolAddress((void**)&y,   g_y);

    // Launch order puts bgemm<0> at index 5 so ncu (-s 5 -c 1) profiles it.
    detect_kernel<<<1, 4>>>(w_attn_q, w_proj_q, b_attn_q, b_proj_q);       // 0
    convert_hilo<<<1024, 256>>>(x, xhi, xlo, (size_t)MM*KK);               // 1
    convert_w_bf16<<<1024, 256>>>(w_attn_q, wa_bf, 0, (size_t)N_QKV*KK);   // 2
    convert_bias_kernel<<<12, 256>>>(b_attn_q, s_b_attn, ba, 2, N_QKV);    // 3
    convert_bias_kernel<<<8, 256>>>(b_proj_q, s_b_proj, bp, 3, N_PROJ);    // 4

    {   // 5: QKV projection (tensor cores) -> g_q/g_k/g_v
        dim3 grid(N_QKV/128, MM/128);
        bgemm_kernel<0><<<grid, 256>>>(s_w_attn, ba, nullptr);
    }
    {   // 6: causal flash attention -> g_y
        dim3 grid(BB*HH, TT/64);
        attn_kernel<<<grid, 256>>>();
    }
    convert_w_bf16<<<1024, 256>>>(w_proj_q, wp_bf, 1, (size_t)N_PROJ*KK);  // 7
    convert_hilo<<<1024, 256>>>(y, yhi, ylo, (size_t)MM*KK);               // 8
    {   // 9: output projection -> d_out
        dim3 grid(N_PROJ/128, MM/128);
        bgemm_kernel<1><<<grid, 256>>>(s_w_proj, bp, out);
    }
}

// round 13
// speedup vs baseline: 6.1867x; 4.0297x over previous
#include <cuda_runtime.h>
#include <cuda_bf16.h>
#include <math.h>
#include <stdint.h>

// Problem constants
#define BB 4
#define TT 1024
#define CC 2048
#define HH 16
#define DD 128
#define MM (BB*TT)          // 4096
#define KK CC               // 2048
#define N_QKV (3*CC)        // 6144
#define N_PROJ CC           // 2048
#define ATTN_SCALE 0.088388347648318447f  // 1/sqrt(128)
#define MASK_NEG (-1.0e30f)

// Device-global scratch (no runtime allocation)
__device__ __nv_bfloat16 g_wa_bf[(size_t)N_QKV*KK];
__device__ __nv_bfloat16 g_wp_bf[(size_t)N_PROJ*KK];
__device__ __nv_bfloat16 g_xhi[(size_t)MM*KK];
__device__ __nv_bfloat16 g_xlo[(size_t)MM*KK];
__device__ __nv_bfloat16 g_yhi[(size_t)MM*KK];
__device__ __nv_bfloat16 g_ylo[(size_t)MM*KK];
// q/k in [B,H,T,D]; V stored TRANSPOSED [B,H,D,T]; bf16 hi/lo pairs
__device__ __nv_bfloat16 g_qhi[(size_t)BB*HH*TT*DD];
__device__ __nv_bfloat16 g_qlo[(size_t)BB*HH*TT*DD];
__device__ __nv_bfloat16 g_khi[(size_t)BB*HH*TT*DD];
__device__ __nv_bfloat16 g_klo[(size_t)BB*HH*TT*DD];
__device__ __nv_bfloat16 g_vThi[(size_t)BB*HH*DD*TT];
__device__ __nv_bfloat16 g_vTlo[(size_t)BB*HH*DD*TT];
__device__ float g_bias_a[N_QKV];
__device__ float g_bias_p[N_PROJ];
__device__ int g_flag[4];   // 0:wa 1:wp 2:ba 3:bp ; 0=i8,1=i32,2=f32

// ---------------------------------------------------------------------------
// dtype detection (harness promotes int8 arrays to int32/f32 storage)
// ---------------------------------------------------------------------------
__device__ int detect_words(const unsigned int* w, int nwords)
{
    bool i32 = true, f32 = true;
    for (int i = 0; i < nwords; ++i) {
        unsigned int v = w[i];
        if (!(v < 0x80u || v >= 0xFFFFFF80u)) i32 = false;
        float f = __uint_as_float(v);
        if (!(fabsf(f) <= 128.0f && f == truncf(f))) f32 = false;
        if (!i32 && !f32) break;
    }
    return i32 ? 1 : (f32 ? 2 : 0);
}

__global__ void detect_kernel(const void* wa, const void* wp,
                              const void* ba, const void* bp)
{
    const int t = threadIdx.x;
    if (t == 0) g_flag[0] = detect_words((const unsigned int*)wa, 256);
    if (t == 1) g_flag[1] = detect_words((const unsigned int*)wp, 256);
    if (t == 2) g_flag[2] = detect_words((const unsigned int*)ba, 256);
    if (t == 3) g_flag[3] = detect_words((const unsigned int*)bp, 256);
}

__device__ __forceinline__ int load_qval(const void* src, int f, size_t i)
{
    if (f == 1) return ((const int*)src)[i];
    if (f == 2) return __float2int_rn(((const float*)src)[i]);
    return (int)((const signed char*)src)[i];
}

// Fused prep: wa->bf16, x->hi/lo, biases->float
__global__ void prep_all(const void* wa, const float* __restrict__ x,
                         const void* ba, const void* bp,
                         const float* s_ba, const float* s_bp)
{
    const int bid = blockIdx.x;
    const int tid = threadIdx.x;
    if (bid < 1024) {
        const int f = g_flag[0];
        const size_t n = (size_t)N_QKV*KK;
        const size_t stride = 1024*256;
        for (size_t i = (size_t)bid*256 + tid; i < n; i += stride)
            g_wa_bf[i] = __float2bfloat16_rn((float)load_qval(wa, f, i));
    } else if (bid < 2048) {
        const size_t n = (size_t)MM*KK;
        const size_t stride = 1024*256;
        for (size_t i = (size_t)(bid-1024)*256 + tid; i < n; i += stride) {
            float v = x[i];
            __nv_bfloat16 h = __float2bfloat16_rn(v);
            g_xhi[i] = h;
            g_xlo[i] = __float2bfloat16_rn(v - __bfloat162float(h));
        }
    } else if (bid == 2048) {
        const int f = g_flag[2];
        const float sb = s_ba[0];
        for (int i = tid; i < N_QKV; i += 256)
            g_bias_a[i] = sb * (float)load_qval(ba, f, i);
    } else {
        const int f = g_flag[3];
        const float sb = s_bp[0];
        for (int i = tid; i < N_PROJ; i += 256)
            g_bias_p[i] = sb * (float)load_qval(bp, f, i);
    }
}

__global__ void prep_wp(const void* wp)
{
    const int f = g_flag[1];
    const size_t n = (size_t)N_PROJ*KK;
    const size_t stride = (size_t)gridDim.x*blockDim.x;
    for (size_t i = (size_t)blockIdx.x*blockDim.x + threadIdx.x; i < n; i += stride)
        g_wp_bf[i] = __float2bfloat16_rn((float)load_qval(wp, f, i));
}

// ---------------------------------------------------------------------------
// mma helpers (validated round 7)
// ---------------------------------------------------------------------------
__device__ __forceinline__ void ldsm_x4(uint32_t& r0, uint32_t& r1,
                                        uint32_t& r2, uint32_t& r3, uint32_t a)
{
    asm volatile("ldmatrix.sync.aligned.m8n8.x4.shared.b16 {%0,%1,%2,%3}, [%4];"
                 : "=r"(r0), "=r"(r1), "=r"(r2), "=r"(r3) : "r"(a));
}
__device__ __forceinline__ void ldsm_x2(uint32_t& r0, uint32_t& r1, uint32_t a)
{
    asm volatile("ldmatrix.sync.aligned.m8n8.x2.shared.b16 {%0,%1}, [%2];"
                 : "=r"(r0), "=r"(r1) : "r"(a));
}
__device__ __forceinline__ void mma_bf16(float* c, const uint32_t* a,
                                         const uint32_t* b)
{
    asm volatile(
        "mma.sync.aligned.m16n8k16.row.col.f32.bf16.bf16.f32 "
        "{%0,%1,%2,%3},{%4,%5,%6,%7},{%8,%9},{%0,%1,%2,%3};"
        : "+f"(c[0]), "+f"(c[1]), "+f"(c[2]), "+f"(c[3])
        : "r"(a[0]), "r"(a[1]), "r"(a[2]), "r"(a[3]), "r"(b[0]), "r"(b[1]));
}

// ---------------------------------------------------------------------------
// Tensor-core GEMM: BM=BN=128, BK=32, 8 warps (2x4)
// MODE 0: epilogue emits q/k bf16 hi/lo (q pre-scaled) + V TRANSPOSED hi/lo.
// MODE 1: fp32 out.
// ---------------------------------------------------------------------------
#define APAD 40

template<int MODE>
__global__ void __launch_bounds__(256) bgemm_kernel(
    const float* __restrict__ sW,
    float* __restrict__ out)
{
    const __nv_bfloat16* Ahi = (MODE == 0) ? g_xhi : g_yhi;
    const __nv_bfloat16* Alo = (MODE == 0) ? g_xlo : g_ylo;
    const __nv_bfloat16* Bw  = (MODE == 0) ? g_wa_bf : g_wp_bf;
    const float* biasf       = (MODE == 0) ? g_bias_a : g_bias_p;
    const int Nn = (MODE == 0) ? N_QKV : N_PROJ;

    __shared__ __nv_bfloat16 Ash[128][APAD];
    __shared__ __nv_bfloat16 Asl[128][APAD];
    __shared__ __nv_bfloat16 Bsh[128][APAD];

    const int tid  = threadIdx.x;
    const int bx   = blockIdx.x;
    const int by   = blockIdx.y;
    const int w    = tid >> 5;
    const int lane = tid & 31;
    const int wm   = w >> 2;
    const int wn   = w & 3;

    float acc[4][4][4];
#pragma unroll
    for (int i = 0; i < 4; ++i)
#pragma unroll
        for (int j = 0; j < 4; ++j)
#pragma unroll
            for (int c = 0; c < 4; ++c) acc[i][j][c] = 0.f;

    const uint32_t a_hi_base = (uint32_t)__cvta_generic_to_shared(&Ash[0][0]);
    const uint32_t a_lo_base = (uint32_t)__cvta_generic_to_shared(&Asl[0][0]);
    const uint32_t b_base    = (uint32_t)__cvta_generic_to_shared(&Bsh[0][0]);
    const int a_row = wm*64 + ((lane >> 3) & 1)*8 + (lane & 7);
    const int a_col = (lane >> 4)*8;
    const uint32_t a_off = (uint32_t)(a_row*APAD + a_col)*2;
    const int l2 = lane & 15;
    const int b_row = wn*32 + (l2 & 7);
    const int b_col = (l2 >> 3)*8;
    const uint32_t b_off = (uint32_t)(b_row*APAD + b_col)*2;

    for (int kt = 0; kt < KK/32; ++kt) {
#pragma unroll
        for (int p = 0; p < 2; ++p) {
            const int idx = tid + p*256;
            const int row = idx >> 2;
            const int seg = idx & 3;
            const size_t goff = (size_t)(by*128 + row)*KK + kt*32 + seg*8;
            *(uint4*)&Ash[row][seg*8] = *(const uint4*)(Ahi + goff);
            *(uint4*)&Asl[row][seg*8] = *(const uint4*)(Alo + goff);
            const size_t boff = (size_t)(bx*128 + row)*KK + kt*32 + seg*8;
            *(uint4*)&Bsh[row][seg*8] = *(const uint4*)(Bw + boff);
        }
        __syncthreads();

#pragma unroll
        for (int kf = 0; kf < 2; ++kf) {
            const uint32_t kfb = (uint32_t)(kf*16*2);
            uint32_t bfr[4][2];
#pragma unroll
            for (int j = 0; j < 4; ++j)
                ldsm_x2(bfr[j][0], bfr[j][1],
                        b_base + b_off + (uint32_t)(j*8*APAD*2) + kfb);
#pragma unroll
            for (int i = 0; i < 4; ++i) {
                uint32_t a[4];
                const uint32_t ao = a_off + (uint32_t)(i*16*APAD*2) + kfb;
                ldsm_x4(a[0], a[1], a[2], a[3], a_hi_base + ao);
#pragma unroll
                for (int j = 0; j < 4; ++j) mma_bf16(acc[i][j], a, bfr[j]);
                ldsm_x4(a[0], a[1], a[2], a[3], a_lo_base + ao);
#pragma unroll
                for (int j = 0; j < 4; ++j) mma_bf16(acc[i][j], a, bfr[j]);
            }
        }
        __syncthreads();
    }

    const float sw = sW[0];
    const int mrow = (lane >> 2);
    const int ncol = 2*(lane & 3);
#pragma unroll
    for (int i = 0; i < 4; ++i) {
#pragma unroll
        for (int j = 0; j < 4; ++j) {
#pragma unroll
            for (int c = 0; c < 4; ++c) {
                const int m = by*128 + wm*64 + i*16 + mrow + ((c >> 1) ? 8 : 0);
                const int n = bx*128 + wn*32 + j*8 + ncol + (c & 1);
                float v = sw * acc[i][j][c] + biasf[n];
                if (MODE == 1) {
                    out[(size_t)m*Nn + n] = v;
                } else {
                    const int which = n >> 11;       // 0:q 1:k 2:v
                    const int cc = n & 2047;
                    const int hh = cc >> 7;
                    const int dd = cc & 127;
                    const int b_ = m >> 10;
                    const int t_ = m & 1023;
                    if (which == 0) v *= ATTN_SCALE;
                    __nv_bfloat16 hi = __float2bfloat16_rn(v);
                    __nv_bfloat16 lo = __float2bfloat16_rn(v - __bfloat162float(hi));
                    if (which == 2) {
                        // transposed V: [B,H,D,T]
                        const size_t offT = ((size_t)(b_*HH + hh)*DD + dd)*TT + t_;
                        g_vThi[offT] = hi; g_vTlo[offT] = lo;
                    } else {
                        const size_t off = (size_t)((b_*HH + hh)*TT + t_)*DD + dd;
                        if (which == 0) { g_qhi[off] = hi; g_qlo[off] = lo; }
                        else            { g_khi[off] = hi; g_klo[off] = lo; }
                    }
                }
            }
        }
    }
}

// ---------------------------------------------------------------------------
// Tensor-core flash attention. Block = (b,h) x 64-q-rows, 128 threads (4 warps).
// Warp w owns q rows [w*16, w*16+16). K-tiles of 32 keys.
// Finite masking only. V pre-transposed -> PV uses non-trans ldsm B path.
// ---------------------------------------------------------------------------
#define QSTR 136     // row stride (bf16) for 128-wide tiles
#define PSTR 40      // row stride for 32-wide tiles (P, VT)
#define ATTN_SMEM_BYTES ((2*64*QSTR + 2*32*QSTR + 2*128*PSTR + 2*64*PSTR)*2) // 82944

__global__ void __launch_bounds__(128) attn_mma_kernel()
{
    extern __shared__ __nv_bfloat16 smem[];
    __nv_bfloat16* Qh  = smem;                 // 64 x QSTR
    __nv_bfloat16* Ql  = Qh  + 64*QSTR;
    __nv_bfloat16* Kh  = Ql  + 64*QSTR;        // 32 x QSTR
    __nv_bfloat16* Kl  = Kh  + 32*QSTR;
    __nv_bfloat16* VhT = Kl  + 32*QSTR;        // 128 x PSTR (dims x keys)
    __nv_bfloat16* VlT = VhT + 128*PSTR;
    __nv_bfloat16* Ph  = VlT + 128*PSTR;       // 64 x PSTR
    __nv_bfloat16* Pl  = Ph  + 64*PSTR;

    const int bh = blockIdx.x;
    const int qt = blockIdx.y;
    const int tid = threadIdx.x;
    const int w = tid >> 5;
    const int lane = tid & 31;
    const int l2 = lane & 15;

    // Q tile: 64 rows x 16 segs = 1024 uint4 per buffer; 128 thr x 8 iters
    {
        const __nv_bfloat16* qh = g_qhi + (size_t)bh*TT*DD + (size_t)qt*64*DD;
        const __nv_bfloat16* ql = g_qlo + (size_t)bh*TT*DD + (size_t)qt*64*DD;
#pragma unroll
        for (int it = 0; it < 8; ++it) {
            const int idx = tid + it*128;        // 0..1023
            const int row = idx >> 4, seg = idx & 15;
            *(uint4*)&Qh[row*QSTR + seg*8] = *(const uint4*)(qh + row*128 + seg*8);
            *(uint4*)&Ql[row*QSTR + seg*8] = *(const uint4*)(ql + row*128 + seg*8);
        }
    }

    const uint32_t qh_b  = (uint32_t)__cvta_generic_to_shared(Qh);
    const uint32_t ql_b  = (uint32_t)__cvta_generic_to_shared(Ql);
    const uint32_t kh_b  = (uint32_t)__cvta_generic_to_shared(Kh);
    const uint32_t kl_b  = (uint32_t)__cvta_generic_to_shared(Kl);
    const uint32_t vhT_b = (uint32_t)__cvta_generic_to_shared(VhT);
    const uint32_t vlT_b = (uint32_t)__cvta_generic_to_shared(VlT);
    const uint32_t ph_b  = (uint32_t)__cvta_generic_to_shared(Ph);
    const uint32_t pl_b  = (uint32_t)__cvta_generic_to_shared(Pl);

    const int a_row_q = w*16 + ((lane >> 3) & 1)*8 + (lane & 7);
    const int acolsel = (lane >> 4)*8;
    const int b_row_k = (l2 & 7);
    const int bcolsel = (l2 >> 3)*8;

    float o[16][4];
#pragma unroll
    for (int nf = 0; nf < 16; ++nf)
#pragma unroll
        for (int c = 0; c < 4; ++c) o[nf][c] = 0.f;

    float m_run0 = MASK_NEG, m_run1 = MASK_NEG;
    float l_run0 = 0.f, l_run1 = 0.f;

    const int r0 = lane >> 2;
    const int qcol = 2*(lane & 3);
    const int grow0 = qt*64 + w*16 + r0;
    const int grow1 = grow0 + 8;
    const int nkt = 2*qt + 2;

    for (int kt = 0; kt < nkt; ++kt) {
        __syncthreads();
        // K tile: 32 rows x 16 segs = 512 uint4/buffer; VT: 128 rows x 4 segs
        {
            const size_t kbase = (size_t)bh*TT*DD + (size_t)kt*32*DD;
#pragma unroll
            for (int it = 0; it < 4; ++it) {
                const int idx = tid + it*128;    // 0..511
                const int row = idx >> 4, seg = idx & 15;
                const size_t go = kbase + row*128 + seg*8;
                *(uint4*)&Kh[row*QSTR + seg*8] = *(const uint4*)(g_khi + go);
                *(uint4*)&Kl[row*QSTR + seg*8] = *(const uint4*)(g_klo + go);
            }
            const size_t vtbase = (size_t)bh*DD*TT + (size_t)kt*32;
#pragma unroll
            for (int it = 0; it < 4; ++it) {
                const int idx = tid + it*128;    // 0..511
                const int row = idx >> 2, seg = idx & 3;
                const size_t go = vtbase + (size_t)row*TT + seg*8;
                *(uint4*)&VhT[row*PSTR + seg*8] = *(const uint4*)(g_vThi + go);
                *(uint4*)&VlT[row*PSTR + seg*8] = *(const uint4*)(g_vTlo + go);
            }
        }
        __syncthreads();

        // S = Q K^T (16x32 per warp), 3 precision chains
        float s[4][4];
#pragma unroll
        for (int j = 0; j < 4; ++j)
#pragma unroll
            for (int c = 0; c < 4; ++c) s[j][c] = 0.f;

#pragma unroll
        for (int kd = 0; kd < 8; ++kd) {
            const uint32_t aoff = (uint32_t)(a_row_q*QSTR + kd*16 + acolsel)*2;
            uint32_t ah[4], al[4];
            ldsm_x4(ah[0], ah[1], ah[2], ah[3], qh_b + aoff);
            ldsm_x4(al[0], al[1], al[2], al[3], ql_b + aoff);
#pragma unroll
            for (int j = 0; j < 4; ++j) {
                const uint32_t boff = (uint32_t)((j*8 + b_row_k)*QSTR + kd*16 + bcolsel)*2;
                uint32_t bh2[2], bl2[2];
                ldsm_x2(bh2[0], bh2[1], kh_b + boff);
                ldsm_x2(bl2[0], bl2[1], kl_b + boff);
                mma_bf16(s[j], ah, bh2);
                mma_bf16(s[j], ah, bl2);
                mma_bf16(s[j], al, bh2);
            }
        }

        // finite mask + online softmax (warp-local rows)
        float m0 = MASK_NEG, m1 = MASK_NEG;
#pragma unroll
        for (int j = 0; j < 4; ++j) {
#pragma unroll
            for (int c = 0; c < 4; ++c) {
                const int gcol = kt*32 + j*8 + qcol + (c & 1);
                const int grow = (c < 2) ? grow0 : grow1;
                if (gcol > grow) s[j][c] = MASK_NEG;
            }
            m0 = fmaxf(m0, fmaxf(s[j][0], s[j][1]));
            m1 = fmaxf(m1, fmaxf(s[j][2], s[j][3]));
        }
        m0 = fmaxf(m0, __shfl_xor_sync(0xffffffffu, m0, 1));
        m0 = fmaxf(m0, __shfl_xor_sync(0xffffffffu, m0, 2));
        m1 = fmaxf(m1, __shfl_xor_sync(0xffffffffu, m1, 1));
        m1 = fmaxf(m1, __shfl_xor_sync(0xffffffffu, m1, 2));

        const float mn0 = fmaxf(m_run0, m0);
        const float mn1 = fmaxf(m_run1, m1);
        const float al0 = __expf(m_run0 - mn0);
        const float al1 = __expf(m_run1 - mn1);
        m_run0 = mn0; m_run1 = mn1;

        float ls0 = 0.f, ls1 = 0.f;
#pragma unroll
        for (int j = 0; j < 4; ++j) {
            s[j][0] = __expf(s[j][0] - mn0);
            s[j][1] = __expf(s[j][1] - mn0);
            s[j][2] = __expf(s[j][2] - mn1);
            s[j][3] = __expf(s[j][3] - mn1);
            ls0 += s[j][0] + s[j][1];
            ls1 += s[j][2] + s[j][3];
        }
        ls0 += __shfl_xor_sync(0xffffffffu, ls0, 1);
        ls0 += __shfl_xor_sync(0xffffffffu, ls0, 2);
        ls1 += __shfl_xor_sync(0xffffffffu, ls1, 1);
        ls1 += __shfl_xor_sync(0xffffffffu, ls1, 2);
        l_run0 = l_run0*al0 + ls0;
        l_run1 = l_run1*al1 + ls1;

        // write P hi/lo to smem (C-fragment layout == bgemm epilogue layout)
        const int prow0 = w*16 + r0;
#pragma unroll
        for (int j = 0; j < 4; ++j) {
            const int pc = j*8 + qcol;
            float p0 = s[j][0], p1 = s[j][1];
            __nv_bfloat16 h0 = __float2bfloat16_rn(p0);
            __nv_bfloat16 h1 = __float2bfloat16_rn(p1);
            *(__nv_bfloat162*)&Ph[prow0*PSTR + pc] = __nv_bfloat162(h0, h1);
            *(__nv_bfloat162*)&Pl[prow0*PSTR + pc] = __nv_bfloat162(
                __float2bfloat16_rn(p0 - __bfloat162float(h0)),
                __float2bfloat16_rn(p1 - __bfloat162float(h1)));
            float p2 = s[j][2], p3 = s[j][3];
            __nv_bfloat16 h2 = __float2bfloat16_rn(p2);
            __nv_bfloat16 h3 = __float2bfloat16_rn(p3);
            *(__nv_bfloat162*)&Ph[(prow0+8)*PSTR + pc] = __nv_bfloat162(h2, h3);
            *(__nv_bfloat162*)&Pl[(prow0+8)*PSTR + pc] = __nv_bfloat162(
                __float2bfloat16_rn(p2 - __bfloat162float(h2)),
                __float2bfloat16_rn(p3 - __bfloat162float(h3)));
        }
        __syncwarp();

#pragma unroll
        for (int nf = 0; nf < 16; ++nf) {
            o[nf][0] *= al0; o[nf][1] *= al0;
            o[nf][2] *= al1; o[nf][3] *= al1;
        }

        // O += P V : B from transposed-V smem (non-trans ldsm path)
#pragma unroll
        for (int kf = 0; kf < 2; ++kf) {
            const uint32_t paoff = (uint32_t)(a_row_q*PSTR + kf*16 + acolsel)*2;
            uint32_t pah[4], pal[4];
            ldsm_x4(pah[0], pah[1], pah[2], pah[3], ph_b + paoff);
            ldsm_x4(pal[0], pal[1], pal[2], pal[3], pl_b + paoff);
#pragma unroll
            for (int nf = 0; nf < 16; ++nf) {
                const uint32_t boffV =
                    (uint32_t)((nf*8 + b_row_k)*PSTR + kf*16 + bcolsel)*2;
                uint32_t vbh[2], vbl[2];
                ldsm_x2(vbh[0], vbh[1], vhT_b + boffV);
                ldsm_x2(vbl[0], vbl[1], vlT_b + boffV);
                mma_bf16(o[nf], pah, vbh);
                mma_bf16(o[nf], pah, vbl);
                mma_bf16(o[nf], pal, vbh);
            }
        }
        __syncwarp();
    }

    // epilogue: y = O / l -> bf16 hi/lo
    const float li0 = 1.0f / l_run0;
    const float li1 = 1.0f / l_run1;
    const int b_ = bh >> 4;
    const int h_ = bh & 15;
    const int t0 = qt*64 + w*16 + r0;
    const int t1 = t0 + 8;
#pragma unroll
    for (int nf = 0; nf < 16; ++nf) {
        const int dim = nf*8 + qcol;
        {
            float v0 = o[nf][0]*li0, v1 = o[nf][1]*li0;
            __nv_bfloat16 h0 = __float2bfloat16_rn(v0);
            __nv_bfloat16 h1 = __float2bfloat16_rn(v1);
            const size_t off = (size_t)(b_*TT + t0)*CC + h_*DD + dim;
            *(__nv_bfloat162*)&g_yhi[off] = __nv_bfloat162(h0, h1);
            *(__nv_bfloat162*)&g_ylo[off] = __nv_bfloat162(
                __float2bfloat16_rn(v0 - __bfloat162float(h0)),
                __float2bfloat16_rn(v1 - __bfloat162float(h1)));
        }
        {
            float v2 = o[nf][2]*li1, v3 = o[nf][3]*li1;
            __nv_bfloat16 h2 = __float2bfloat16_rn(v2);
            __nv_bfloat16 h3 = __float2bfloat16_rn(v3);
            const size_t off = (size_t)(b_*TT + t1)*CC + h_*DD + dim;
            *(__nv_bfloat162*)&g_yhi[off] = __nv_bfloat162(h2, h3);
            *(__nv_bfloat162*)&g_ylo[off] = __nv_bfloat162(
                __float2bfloat16_rn(v2 - __bfloat162float(h2)),
                __float2bfloat16_rn(v3 - __bfloat162float(h3)));
        }
    }
}

// ---------------------------------------------------------------------------
extern "C" void kernel_launch(void* const* d_in, const int* in_sizes, int n_in,
                              void* d_out, int out_size)
{
    int i_x = -1, i_wa = -1, i_ba = -1, i_wp = -1, i_bp = -1;
    for (int i = 0; i < n_in; ++i) {
        switch (in_sizes[i]) {
            case 8388608:  i_x  = i; break;
            case 12582912: i_wa = i; break;
            case 6144:     i_ba = i; break;
            case 4194304:  i_wp = i; break;
            case 2048:     i_bp = i; break;
            default: break;
        }
    }
    auto find_scale = [&](int start) -> int {
        for (int j = start + 1; j < n_in; ++j)
            if (in_sizes[j] <= 1) return j;
        return -1;
    };
    const int i_swa = find_scale(i_wa);
    const int i_sba = find_scale(i_ba);
    const int i_swp = find_scale(i_wp);
    const int i_sbp = find_scale(i_bp);

    const float* x        = (const float*)d_in[i_x];
    const void*  w_attn_q = d_in[i_wa];
    const float* s_w_attn = (const float*)d_in[i_swa];
    const void*  b_attn_q = d_in[i_ba];
    const float* s_b_attn = (const float*)d_in[i_sba];
    const void*  w_proj_q = d_in[i_wp];
    const float* s_w_proj = (const float*)d_in[i_swp];
    const void*  b_proj_q = d_in[i_bp];
    const float* s_b_proj = (const float*)d_in[i_sbp];
    float* out = (float*)d_out;

    cudaFuncSetAttribute(attn_mma_kernel,
                         cudaFuncAttributeMaxDynamicSharedMemorySize,
                         ATTN_SMEM_BYTES);

    // 0: dtype detect
    detect_kernel<<<1, 4>>>(w_attn_q, w_proj_q, b_attn_q, b_proj_q);
    // 1: fused prep (wa->bf16, x->hi/lo, biases)
    prep_all<<<2050, 256>>>(w_attn_q, x, b_attn_q, b_proj_q, s_b_attn, s_b_proj);
    // 2: wp->bf16
    prep_wp<<<512, 256>>>(w_proj_q);
    // 3: QKV projection -> q/k hi/lo + transposed V (profiled slot)
    {
        dim3 grid(N_QKV/128, MM/128);
        bgemm_kernel<0><<<grid, 256>>>(s_w_attn, nullptr);
    }
    // 4: tensor-core flash attention -> y bf16 hi/lo
    {
        dim3 grid(BB*HH, TT/64);
        attn_mma_kernel<<<grid, 128, ATTN_SMEM_BYTES>>>();
    }
    // 5: output projection -> d_out (fp32)
    {
        dim3 grid(N_PROJ/128, MM/128);
        bgemm_kernel<1><<<grid, 256>>>(s_w_proj, out);
    }
}

// round 14
// speedup vs baseline: 6.6080x; 1.0681x over previous
#include <cuda_runtime.h>
#include <cuda_bf16.h>
#include <math.h>
#include <stdint.h>

// Problem constants
#define BB 4
#define TT 1024
#define CC 2048
#define HH 16
#define DD 128
#define MM (BB*TT)          // 4096
#define KK CC               // 2048
#define N_QKV (3*CC)        // 6144
#define N_PROJ CC           // 2048
#define ATTN_SCALE 0.088388347648318447f  // 1/sqrt(128)
#define MASK_NEG (-1.0e30f)

// Device-global scratch (no runtime allocation)
__device__ __nv_bfloat16 g_wa_bf[(size_t)N_QKV*KK];
__device__ __nv_bfloat16 g_wp_bf[(size_t)N_PROJ*KK];
__device__ __nv_bfloat16 g_xhi[(size_t)MM*KK];
__device__ __nv_bfloat16 g_xlo[(size_t)MM*KK];
__device__ __nv_bfloat16 g_yhi[(size_t)MM*KK];
__device__ __nv_bfloat16 g_ylo[(size_t)MM*KK];
// q/k in [B,H,T,D]; V stored TRANSPOSED [B,H,D,T]; bf16 hi/lo pairs
__device__ __nv_bfloat16 g_qhi[(size_t)BB*HH*TT*DD];
__device__ __nv_bfloat16 g_qlo[(size_t)BB*HH*TT*DD];
__device__ __nv_bfloat16 g_khi[(size_t)BB*HH*TT*DD];
__device__ __nv_bfloat16 g_klo[(size_t)BB*HH*TT*DD];
__device__ __nv_bfloat16 g_vThi[(size_t)BB*HH*DD*TT];
__device__ __nv_bfloat16 g_vTlo[(size_t)BB*HH*DD*TT];
__device__ float g_bias_a[N_QKV];
__device__ float g_bias_p[N_PROJ];
__device__ int g_flag[4];   // 0:wa 1:wp 2:ba 3:bp ; 0=i8,1=i32,2=f32

// ---------------------------------------------------------------------------
// dtype detection (harness promotes int8 arrays to int32/f32 storage)
// ---------------------------------------------------------------------------
__device__ int detect_words(const unsigned int* w, int nwords)
{
    bool i32 = true, f32 = true;
    for (int i = 0; i < nwords; ++i) {
        unsigned int v = w[i];
        if (!(v < 0x80u || v >= 0xFFFFFF80u)) i32 = false;
        float f = __uint_as_float(v);
        if (!(fabsf(f) <= 128.0f && f == truncf(f))) f32 = false;
        if (!i32 && !f32) break;
    }
    return i32 ? 1 : (f32 ? 2 : 0);
}

__global__ void detect_kernel(const void* wa, const void* wp,
                              const void* ba, const void* bp)
{
    const int t = threadIdx.x;
    if (t == 0) g_flag[0] = detect_words((const unsigned int*)wa, 256);
    if (t == 1) g_flag[1] = detect_words((const unsigned int*)wp, 256);
    if (t == 2) g_flag[2] = detect_words((const unsigned int*)ba, 256);
    if (t == 3) g_flag[3] = detect_words((const unsigned int*)bp, 256);
}

__device__ __forceinline__ int load_qval(const void* src, int f, size_t i)
{
    if (f == 1) return ((const int*)src)[i];
    if (f == 2) return __float2int_rn(((const float*)src)[i]);
    return (int)((const signed char*)src)[i];
}

// Fused prep: wa->bf16, x->hi/lo, biases->float
__global__ void prep_all(const void* wa, const float* __restrict__ x,
                         const void* ba, const void* bp,
                         const float* s_ba, const float* s_bp)
{
    const int bid = blockIdx.x;
    const int tid = threadIdx.x;
    if (bid < 1024) {
        const int f = g_flag[0];
        const size_t n = (size_t)N_QKV*KK;
        const size_t stride = 1024*256;
        for (size_t i = (size_t)bid*256 + tid; i < n; i += stride)
            g_wa_bf[i] = __float2bfloat16_rn((float)load_qval(wa, f, i));
    } else if (bid < 2048) {
        const size_t n = (size_t)MM*KK;
        const size_t stride = 1024*256;
        for (size_t i = (size_t)(bid-1024)*256 + tid; i < n; i += stride) {
            float v = x[i];
            __nv_bfloat16 h = __float2bfloat16_rn(v);
            g_xhi[i] = h;
            g_xlo[i] = __float2bfloat16_rn(v - __bfloat162float(h));
        }
    } else if (bid == 2048) {
        const int f = g_flag[2];
        const float sb = s_ba[0];
        for (int i = tid; i < N_QKV; i += 256)
            g_bias_a[i] = sb * (float)load_qval(ba, f, i);
    } else {
        const int f = g_flag[3];
        const float sb = s_bp[0];
        for (int i = tid; i < N_PROJ; i += 256)
            g_bias_p[i] = sb * (float)load_qval(bp, f, i);
    }
}

__global__ void prep_wp(const void* wp)
{
    const int f = g_flag[1];
    const size_t n = (size_t)N_PROJ*KK;
    const size_t stride = (size_t)gridDim.x*blockDim.x;
    for (size_t i = (size_t)blockIdx.x*blockDim.x + threadIdx.x; i < n; i += stride)
        g_wp_bf[i] = __float2bfloat16_rn((float)load_qval(wp, f, i));
}

// ---------------------------------------------------------------------------
// mma / ldsm / cp.async helpers
// ---------------------------------------------------------------------------
__device__ __forceinline__ void ldsm_x4(uint32_t& r0, uint32_t& r1,
                                        uint32_t& r2, uint32_t& r3, uint32_t a)
{
    asm volatile("ldmatrix.sync.aligned.m8n8.x4.shared.b16 {%0,%1,%2,%3}, [%4];"
                 : "=r"(r0), "=r"(r1), "=r"(r2), "=r"(r3) : "r"(a));
}
__device__ __forceinline__ void ldsm_x2(uint32_t& r0, uint32_t& r1, uint32_t a)
{
    asm volatile("ldmatrix.sync.aligned.m8n8.x2.shared.b16 {%0,%1}, [%2];"
                 : "=r"(r0), "=r"(r1) : "r"(a));
}
__device__ __forceinline__ void mma_bf16(float* c, const uint32_t* a,
                                         const uint32_t* b)
{
    asm volatile(
        "mma.sync.aligned.m16n8k16.row.col.f32.bf16.bf16.f32 "
        "{%0,%1,%2,%3},{%4,%5,%6,%7},{%8,%9},{%0,%1,%2,%3};"
        : "+f"(c[0]), "+f"(c[1]), "+f"(c[2]), "+f"(c[3])
        : "r"(a[0]), "r"(a[1]), "r"(a[2]), "r"(a[3]), "r"(b[0]), "r"(b[1]));
}
__device__ __forceinline__ void cp_async16(uint32_t smem_addr, const void* gptr)
{
    asm volatile("cp.async.cg.shared.global [%0], [%1], 16;"
                 :: "r"(smem_addr), "l"(gptr));
}
__device__ __forceinline__ void cp_commit()
{
    asm volatile("cp.async.commit_group;");
}
template<int N>
__device__ __forceinline__ void cp_wait()
{
    asm volatile("cp.async.wait_group %0;" :: "n"(N));
}

// ---------------------------------------------------------------------------
// Tensor-core GEMM, cp.async double-buffered: BM=BN=128, BK=32, 8 warps (2x4)
// MODE 0: epilogue emits q/k bf16 hi/lo (q pre-scaled) + V TRANSPOSED hi/lo.
// MODE 1: fp32 out.
// ---------------------------------------------------------------------------
#define APAD 40
#define TILE_B (128*APAD*2)            // bytes per 128x32 tile
#define BGEMM_SMEM_BYTES (2*3*TILE_B)  // 61440

template<int MODE>
__global__ void __launch_bounds__(256) bgemm_kernel(
    const float* __restrict__ sW,
    float* __restrict__ out)
{
    const __nv_bfloat16* Ahi = (MODE == 0) ? g_xhi : g_yhi;
    const __nv_bfloat16* Alo = (MODE == 0) ? g_xlo : g_ylo;
    const __nv_bfloat16* Bw  = (MODE == 0) ? g_wa_bf : g_wp_bf;
    const float* biasf       = (MODE == 0) ? g_bias_a : g_bias_p;
    const int Nn = (MODE == 0) ? N_QKV : N_PROJ;

    extern __shared__ __nv_bfloat16 sm[];
    const uint32_t s_base = (uint32_t)__cvta_generic_to_shared(sm);
    // buffer b: [Ahi | Alo | B] each TILE_B bytes
    uint32_t ahi_s[2], alo_s[2], bsh_s[2];
#pragma unroll
    for (int b = 0; b < 2; ++b) {
        ahi_s[b] = s_base + b*3*TILE_B;
        alo_s[b] = ahi_s[b] + TILE_B;
        bsh_s[b] = alo_s[b] + TILE_B;
    }

    const int tid  = threadIdx.x;
    const int bx   = blockIdx.x;
    const int by   = blockIdx.y;
    const int w    = tid >> 5;
    const int lane = tid & 31;
    const int wm   = w >> 2;
    const int wn   = w & 3;

    float acc[4][4][4];
#pragma unroll
    for (int i = 0; i < 4; ++i)
#pragma unroll
        for (int j = 0; j < 4; ++j)
#pragma unroll
            for (int c = 0; c < 4; ++c) acc[i][j][c] = 0.f;

    // fragment addressing
    const int a_row = wm*64 + ((lane >> 3) & 1)*8 + (lane & 7);
    const int a_col = (lane >> 4)*8;
    const uint32_t a_off = (uint32_t)(a_row*APAD + a_col)*2;
    // B x4: lanes0-7 (k0,n j*8+..), 8-15 (k8), 16-23 (k16), 24-31 (k24)
    const int bx4_row = wn*32 + (lane & 7);
    const int bx4_col = (lane >> 3)*8;
    const uint32_t bx4_off = (uint32_t)(bx4_row*APAD + bx4_col)*2;

    // async tile loader
    auto load_tile = [&](int buf, int kt) {
#pragma unroll
        for (int p = 0; p < 2; ++p) {
            const int idx = tid + p*256;
            const int row = idx >> 2;
            const int seg = idx & 3;
            const uint32_t soff = (uint32_t)(row*APAD + seg*8)*2;
            const size_t goff = (size_t)(by*128 + row)*KK + kt*32 + seg*8;
            cp_async16(ahi_s[buf] + soff, Ahi + goff);
            cp_async16(alo_s[buf] + soff, Alo + goff);
            const size_t boff = (size_t)(bx*128 + row)*KK + kt*32 + seg*8;
            cp_async16(bsh_s[buf] + soff, Bw + boff);
        }
        cp_commit();
    };

    const int NT = KK/32;
    load_tile(0, 0);

    for (int kt = 0; kt < NT; ++kt) {
        const int buf = kt & 1;
        if (kt + 1 < NT) {
            load_tile(buf ^ 1, kt + 1);
            cp_wait<1>();
        } else {
            cp_wait<0>();
        }
        __syncthreads();

        // B fragments: one x4 per j covers both kf halves
        uint32_t bfr[4][4];
#pragma unroll
        for (int j = 0; j < 4; ++j)
            ldsm_x4(bfr[j][0], bfr[j][1], bfr[j][2], bfr[j][3],
                    bsh_s[buf] + bx4_off + (uint32_t)(j*8*APAD*2));

#pragma unroll
        for (int kf = 0; kf < 2; ++kf) {
            const uint32_t kfb = (uint32_t)(kf*16*2);
#pragma unroll
            for (int i = 0; i < 4; ++i) {
                uint32_t a[4];
                const uint32_t ao = a_off + (uint32_t)(i*16*APAD*2) + kfb;
                ldsm_x4(a[0], a[1], a[2], a[3], ahi_s[buf] + ao);
#pragma unroll
                for (int j = 0; j < 4; ++j) mma_bf16(acc[i][j], a, &bfr[j][kf*2]);
                ldsm_x4(a[0], a[1], a[2], a[3], alo_s[buf] + ao);
#pragma unroll
                for (int j = 0; j < 4; ++j) mma_bf16(acc[i][j], a, &bfr[j][kf*2]);
            }
        }
        __syncthreads();
    }

    const float sw = sW[0];
    const int mrow = (lane >> 2);
    const int ncol = 2*(lane & 3);
#pragma unroll
    for (int i = 0; i < 4; ++i) {
#pragma unroll
        for (int j = 0; j < 4; ++j) {
#pragma unroll
            for (int c = 0; c < 4; ++c) {
                const int m = by*128 + wm*64 + i*16 + mrow + ((c >> 1) ? 8 : 0);
                const int n = bx*128 + wn*32 + j*8 + ncol + (c & 1);
                float v = sw * acc[i][j][c] + biasf[n];
                if (MODE == 1) {
                    out[(size_t)m*Nn + n] = v;
                } else {
                    const int which = n >> 11;       // 0:q 1:k 2:v
                    const int cc = n & 2047;
                    const int hh = cc >> 7;
                    const int dd = cc & 127;
                    const int b_ = m >> 10;
                    const int t_ = m & 1023;
                    if (which == 0) v *= ATTN_SCALE;
                    __nv_bfloat16 hi = __float2bfloat16_rn(v);
                    __nv_bfloat16 lo = __float2bfloat16_rn(v - __bfloat162float(hi));
                    if (which == 2) {
                        const size_t offT = ((size_t)(b_*HH + hh)*DD + dd)*TT + t_;
                        g_vThi[offT] = hi; g_vTlo[offT] = lo;
                    } else {
                        const size_t off = (size_t)((b_*HH + hh)*TT + t_)*DD + dd;
                        if (which == 0) { g_qhi[off] = hi; g_qlo[off] = lo; }
                        else            { g_khi[off] = hi; g_klo[off] = lo; }
                    }
                }
            }
        }
    }
}

// ---------------------------------------------------------------------------
// Tensor-core flash attention (unchanged from passing round 13).
// Block = (b,h) x 64-q-rows, 128 threads (4 warps).
// ---------------------------------------------------------------------------
#define QSTR 136
#define PSTR 40
#define ATTN_SMEM_BYTES ((2*64*QSTR + 2*32*QSTR + 2*128*PSTR + 2*64*PSTR)*2) // 82944

__global__ void __launch_bounds__(128) attn_mma_kernel()
{
    extern __shared__ __nv_bfloat16 smem[];
    __nv_bfloat16* Qh  = smem;
    __nv_bfloat16* Ql  = Qh  + 64*QSTR;
    __nv_bfloat16* Kh  = Ql  + 64*QSTR;
    __nv_bfloat16* Kl  = Kh  + 32*QSTR;
    __nv_bfloat16* VhT = Kl  + 32*QSTR;
    __nv_bfloat16* VlT = VhT + 128*PSTR;
    __nv_bfloat16* Ph  = VlT + 128*PSTR;
    __nv_bfloat16* Pl  = Ph  + 64*PSTR;

    const int bh = blockIdx.x;
    const int qt = blockIdx.y;
    const int tid = threadIdx.x;
    const int w = tid >> 5;
    const int lane = tid & 31;
    const int l2 = lane & 15;

    {
        const __nv_bfloat16* qh = g_qhi + (size_t)bh*TT*DD + (size_t)qt*64*DD;
        const __nv_bfloat16* ql = g_qlo + (size_t)bh*TT*DD + (size_t)qt*64*DD;
#pragma unroll
        for (int it = 0; it < 8; ++it) {
            const int idx = tid + it*128;
            const int row = idx >> 4, seg = idx & 15;
            *(uint4*)&Qh[row*QSTR + seg*8] = *(const uint4*)(qh + row*128 + seg*8);
            *(uint4*)&Ql[row*QSTR + seg*8] = *(const uint4*)(ql + row*128 + seg*8);
        }
    }

    const uint32_t qh_b  = (uint32_t)__cvta_generic_to_shared(Qh);
    const uint32_t ql_b  = (uint32_t)__cvta_generic_to_shared(Ql);
    const uint32_t kh_b  = (uint32_t)__cvta_generic_to_shared(Kh);
    const uint32_t kl_b  = (uint32_t)__cvta_generic_to_shared(Kl);
    const uint32_t vhT_b = (uint32_t)__cvta_generic_to_shared(VhT);
    const uint32_t vlT_b = (uint32_t)__cvta_generic_to_shared(VlT);
    const uint32_t ph_b  = (uint32_t)__cvta_generic_to_shared(Ph);
    const uint32_t pl_b  = (uint32_t)__cvta_generic_to_shared(Pl);

    const int a_row_q = w*16 + ((lane >> 3) & 1)*8 + (lane & 7);
    const int acolsel = (lane >> 4)*8;
    const int b_row_k = (l2 & 7);
    const int bcolsel = (l2 >> 3)*8;

    float o[16][4];
#pragma unroll
    for (int nf = 0; nf < 16; ++nf)
#pragma unroll
        for (int c = 0; c < 4; ++c) o[nf][c] = 0.f;

    float m_run0 = MASK_NEG, m_run1 = MASK_NEG;
    float l_run0 = 0.f, l_run1 = 0.f;

    const int r0 = lane >> 2;
    const int qcol = 2*(lane & 3);
    const int grow0 = qt*64 + w*16 + r0;
    const int grow1 = grow0 + 8;
    const int nkt = 2*qt + 2;

    for (int kt = 0; kt < nkt; ++kt) {
        __syncthreads();
        {
            const size_t kbase = (size_t)bh*TT*DD + (size_t)kt*32*DD;
#pragma unroll
            for (int it = 0; it < 4; ++it) {
                const int idx = tid + it*128;
                const int row = idx >> 4, seg = idx & 15;
                const size_t go = kbase + row*128 + seg*8;
                *(uint4*)&Kh[row*QSTR + seg*8] = *(const uint4*)(g_khi + go);
                *(uint4*)&Kl[row*QSTR + seg*8] = *(const uint4*)(g_klo + go);
            }
            const size_t vtbase = (size_t)bh*DD*TT + (size_t)kt*32;
#pragma unroll
            for (int it = 0; it < 4; ++it) {
                const int idx = tid + it*128;
                const int row = idx >> 2, seg = idx & 3;
                const size_t go = vtbase + (size_t)row*TT + seg*8;
                *(uint4*)&VhT[row*PSTR + seg*8] = *(const uint4*)(g_vThi + go);
                *(uint4*)&VlT[row*PSTR + seg*8] = *(const uint4*)(g_vTlo + go);
            }
        }
        __syncthreads();

        float s[4][4];
#pragma unroll
        for (int j = 0; j < 4; ++j)
#pragma unroll
            for (int c = 0; c < 4; ++c) s[j][c] = 0.f;

#pragma unroll
        for (int kd = 0; kd < 8; ++kd) {
            const uint32_t aoff = (uint32_t)(a_row_q*QSTR + kd*16 + acolsel)*2;
            uint32_t ah[4], al[4];
            ldsm_x4(ah[0], ah[1], ah[2], ah[3], qh_b + aoff);
            ldsm_x4(al[0], al[1], al[2], al[3], ql_b + aoff);
#pragma unroll
            for (int j = 0; j < 4; ++j) {
                const uint32_t boff = (uint32_t)((j*8 + b_row_k)*QSTR + kd*16 + bcolsel)*2;
                uint32_t bh2[2], bl2[2];
                ldsm_x2(bh2[0], bh2[1], kh_b + boff);
                ldsm_x2(bl2[0], bl2[1], kl_b + boff);
                mma_bf16(s[j], ah, bh2);
                mma_bf16(s[j], ah, bl2);
                mma_bf16(s[j], al, bh2);
            }
        }

        float m0 = MASK_NEG, m1 = MASK_NEG;
#pragma unroll
        for (int j = 0; j < 4; ++j) {
#pragma unroll
            for (int c = 0; c < 4; ++c) {
                const int gcol = kt*32 + j*8 + qcol + (c & 1);
                const int grow = (c < 2) ? grow0 : grow1;
                if (gcol > grow) s[j][c] = MASK_NEG;
            }
            m0 = fmaxf(m0, fmaxf(s[j][0], s[j][1]));
            m1 = fmaxf(m1, fmaxf(s[j][2], s[j][3]));
        }
        m0 = fmaxf(m0, __shfl_xor_sync(0xffffffffu, m0, 1));
        m0 = fmaxf(m0, __shfl_xor_sync(0xffffffffu, m0, 2));
        m1 = fmaxf(m1, __shfl_xor_sync(0xffffffffu, m1, 1));
        m1 = fmaxf(m1, __shfl_xor_sync(0xffffffffu, m1, 2));

        const float mn0 = fmaxf(m_run0, m0);
        const float mn1 = fmaxf(m_run1, m1);
        const float al0 = __expf(m_run0 - mn0);
        const float al1 = __expf(m_run1 - mn1);
        m_run0 = mn0; m_run1 = mn1;

        float ls0 = 0.f, ls1 = 0.f;
#pragma unroll
        for (int j = 0; j < 4; ++j) {
            s[j][0] = __expf(s[j][0] - mn0);
            s[j][1] = __expf(s[j][1] - mn0);
            s[j][2] = __expf(s[j][2] - mn1);
            s[j][3] = __expf(s[j][3] - mn1);
            ls0 += s[j][0] + s[j][1];
            ls1 += s[j][2] + s[j][3];
        }
        ls0 += __shfl_xor_sync(0xffffffffu, ls0, 1);
        ls0 += __shfl_xor_sync(0xffffffffu, ls0, 2);
        ls1 += __shfl_xor_sync(0xffffffffu, ls1, 1);
        ls1 += __shfl_xor_sync(0xffffffffu, ls1, 2);
        l_run0 = l_run0*al0 + ls0;
        l_run1 = l_run1*al1 + ls1;

        const int prow0 = w*16 + r0;
#pragma unroll
        for (int j = 0; j < 4; ++j) {
            const int pc = j*8 + qcol;
            float p0 = s[j][0], p1 = s[j][1];
            __nv_bfloat16 h0 = __float2bfloat16_rn(p0);
            __nv_bfloat16 h1 = __float2bfloat16_rn(p1);
            *(__nv_bfloat162*)&Ph[prow0*PSTR + pc] = __nv_bfloat162(h0, h1);
            *(__nv_bfloat162*)&Pl[prow0*PSTR + pc] = __nv_bfloat162(
                __float2bfloat16_rn(p0 - __bfloat162float(h0)),
                __float2bfloat16_rn(p1 - __bfloat162float(h1)));
            float p2 = s[j][2], p3 = s[j][3];
            __nv_bfloat16 h2 = __float2bfloat16_rn(p2);
            __nv_bfloat16 h3 = __float2bfloat16_rn(p3);
            *(__nv_bfloat162*)&Ph[(prow0+8)*PSTR + pc] = __nv_bfloat162(h2, h3);
            *(__nv_bfloat162*)&Pl[(prow0+8)*PSTR + pc] = __nv_bfloat162(
                __float2bfloat16_rn(p2 - __bfloat162float(h2)),
                __float2bfloat16_rn(p3 - __bfloat162float(h3)));
        }
        __syncwarp();

#pragma unroll
        for (int nf = 0; nf < 16; ++nf) {
            o[nf][0] *= al0; o[nf][1] *= al0;
            o[nf][2] *= al1; o[nf][3] *= al1;
        }

#pragma unroll
        for (int kf = 0; kf < 2; ++kf) {
            const uint32_t paoff = (uint32_t)(a_row_q*PSTR + kf*16 + acolsel)*2;
            uint32_t pah[4], pal[4];
            ldsm_x4(pah[0], pah[1], pah[2], pah[3], ph_b + paoff);
            ldsm_x4(pal[0], pal[1], pal[2], pal[3], pl_b + paoff);
#pragma unroll
            for (int nf = 0; nf < 16; ++nf) {
                const uint32_t boffV =
                    (uint32_t)((nf*8 + b_row_k)*PSTR + kf*16 + bcolsel)*2;
                uint32_t vbh[2], vbl[2];
                ldsm_x2(vbh[0], vbh[1], vhT_b + boffV);
                ldsm_x2(vbl[0], vbl[1], vlT_b + boffV);
                mma_bf16(o[nf], pah, vbh);
                mma_bf16(o[nf], pah, vbl);
                mma_bf16(o[nf], pal, vbh);
            }
        }
        __syncwarp();
    }

    const float li0 = 1.0f / l_run0;
    const float li1 = 1.0f / l_run1;
    const int b_ = bh >> 4;
    const int h_ = bh & 15;
    const int t0 = qt*64 + w*16 + r0;
    const int t1 = t0 + 8;
#pragma unroll
    for (int nf = 0; nf < 16; ++nf) {
        const int dim = nf*8 + qcol;
        {
            float v0 = o[nf][0]*li0, v1 = o[nf][1]*li0;
            __nv_bfloat16 h0 = __float2bfloat16_rn(v0);
            __nv_bfloat16 h1 = __float2bfloat16_rn(v1);
            const size_t off = (size_t)(b_*TT + t0)*CC + h_*DD + dim;
            *(__nv_bfloat162*)&g_yhi[off] = __nv_bfloat162(h0, h1);
            *(__nv_bfloat162*)&g_ylo[off] = __nv_bfloat162(
                __float2bfloat16_rn(v0 - __bfloat162float(h0)),
                __float2bfloat16_rn(v1 - __bfloat162float(h1)));
        }
        {
            float v2 = o[nf][2]*li1, v3 = o[nf][3]*li1;
            __nv_bfloat16 h2 = __float2bfloat16_rn(v2);
            __nv_bfloat16 h3 = __float2bfloat16_rn(v3);
            const size_t off = (size_t)(b_*TT + t1)*CC + h_*DD + dim;
            *(__nv_bfloat162*)&g_yhi[off] = __nv_bfloat162(h2, h3);
            *(__nv_bfloat162*)&g_ylo[off] = __nv_bfloat162(
                __float2bfloat16_rn(v2 - __bfloat162float(h2)),
                __float2bfloat16_rn(v3 - __bfloat162float(h3)));
        }
    }
}

// ---------------------------------------------------------------------------
extern "C" void kernel_launch(void* const* d_in, const int* in_sizes, int n_in,
                              void* d_out, int out_size)
{
    int i_x = -1, i_wa = -1, i_ba = -1, i_wp = -1, i_bp = -1;
    for (int i = 0; i < n_in; ++i) {
        switch (in_sizes[i]) {
            case 8388608:  i_x  = i; break;
            case 12582912: i_wa = i; break;
            case 6144:     i_ba = i; break;
            case 4194304:  i_wp = i; break;
            case 2048:     i_bp = i; break;
            default: break;
        }
    }
    auto find_scale = [&](int start) -> int {
        for (int j = start + 1; j < n_in; ++j)
            if (in_sizes[j] <= 1) return j;
        return -1;
    };
    const int i_swa = find_scale(i_wa);
    const int i_sba = find_scale(i_ba);
    const int i_swp = find_scale(i_wp);
    const int i_sbp = find_scale(i_bp);

    const float* x        = (const float*)d_in[i_x];
    const void*  w_attn_q = d_in[i_wa];
    const float* s_w_attn = (const float*)d_in[i_swa];
    const void*  b_attn_q = d_in[i_ba];
    const float* s_b_attn = (const float*)d_in[i_sba];
    const void*  w_proj_q = d_in[i_wp];
    const float* s_w_proj = (const float*)d_in[i_swp];
    const void*  b_proj_q = d_in[i_bp];
    const float* s_b_proj = (const float*)d_in[i_sbp];
    float* out = (float*)d_out;

    cudaFuncSetAttribute(attn_mma_kernel,
                         cudaFuncAttributeMaxDynamicSharedMemorySize,
                         ATTN_SMEM_BYTES);
    cudaFuncSetAttribute(bgemm_kernel<0>,
                         cudaFuncAttributeMaxDynamicSharedMemorySize,
                         BGEMM_SMEM_BYTES);
    cudaFuncSetAttribute(bgemm_kernel<1>,
                         cudaFuncAttributeMaxDynamicSharedMemorySize,
                         BGEMM_SMEM_BYTES);

    // 0: dtype detect
    detect_kernel<<<1, 4>>>(w_attn_q, w_proj_q, b_attn_q, b_proj_q);
    // 1: fused prep (wa->bf16, x->hi/lo, biases)
    prep_all<<<2050, 256>>>(w_attn_q, x, b_attn_q, b_proj_q, s_b_attn, s_b_proj);
    // 2: wp->bf16
    prep_wp<<<512, 256>>>(w_proj_q);
    // 3: QKV projection -> q/k hi/lo + transposed V (profiled slot)
    {
        dim3 grid(N_QKV/128, MM/128);
        bgemm_kernel<0><<<grid, 256, BGEMM_SMEM_BYTES>>>(s_w_attn, nullptr);
    }
    // 4: tensor-core flash attention -> y bf16 hi/lo
    {
        dim3 grid(BB*HH, TT/64);
        attn_mma_kernel<<<grid, 128, ATTN_SMEM_BYTES>>>();
    }
    // 5: output projection -> d_out (fp32)
    {
        dim3 grid(N_PROJ/128, MM/128);
        bgemm_kernel<1><<<grid, 256, BGEMM_SMEM_BYTES>>>(s_w_proj, out);
    }
}